// round 6
// baseline (speedup 1.0000x reference)
#include <cuda_runtime.h>

#define BATCH 32
#define IMH   512
#define IMW   512
#define NBOX  6
#define PSZ   512

// Per-box precomputed data: int4 = (y0, x0, h, w) [h=0 when invalid],
// float2 = (512/hf, 512/wf)
__device__ int4   g_box[BATCH * NBOX];
__device__ float2 g_scl[BATCH * NBOX];

// ---------------------------------------------------------------------------
// Prep: replicate _patch_boxes + int casts bit-exactly (no FMA contraction).
// boxes layout: [B, N, 4] = (ymin, xmin, ymax, xmax)
// ---------------------------------------------------------------------------
__global__ void prep_kernel(const float* __restrict__ boxes) {
    int i = blockIdx.x * blockDim.x + threadIdx.x;
    if (i >= BATCH * NBOX) return;
    float ymin = boxes[i * 4 + 0];
    float xmin = boxes[i * 4 + 1];
    float ymax = boxes[i * 4 + 2];
    float xmax = boxes[i * 4 + 3];

    float h  = __fsub_rn(ymax, ymin);
    float w  = __fsub_rn(xmax, xmin);
    float pw = __fmul_rn(h, 0.5f);        // SCALE = 0.5
    float ph = pw;                         // ASPECT = 1.0 (exact)
    float oy = __fadd_rn(ymin, __fmul_rn(h, 0.5f));
    float ox = __fadd_rn(xmin, __fmul_rn(w, 0.5f));
    float yp = fmaxf(__fsub_rn(oy, __fmul_rn(ph, 0.5f)), 0.0f);
    float xp = fmaxf(__fsub_rn(ox, __fmul_rn(pw, 0.5f)), 0.0f);
    if (__fadd_rn(yp, ph) > (float)IMH) yp = __fsub_rn((float)IMH, ph);
    if (__fadd_rn(xp, pw) > (float)IMW) xp = __fsub_rn((float)IMW, pw);
    bool valid = (ph > 60.0f);             // MIN_PH

    int y0 = (int)yp;                      // astype(int32) = truncation (nonneg)
    int x0 = (int)xp;
    int hi = (int)ph;
    int wi = (int)pw;

    int4 bx;
    bx.x = y0; bx.y = x0;
    bx.z = valid ? hi : 0;                 // h=0 kills the inside test
    bx.w = wi;
    g_box[i] = bx;

    float2 f;
    f.x = __fdiv_rn((float)PSZ, (float)max(hi, 1));
    f.y = __fdiv_rn((float)PSZ, (float)max(wi, 1));
    g_scl[i] = f;
}

// ---------------------------------------------------------------------------
// Main paste kernel: 1 thread = 4 consecutive pixels (3 x float4).
// 256 blocks per image -> single batch index per block.
// ---------------------------------------------------------------------------
__global__ __launch_bounds__(256) void paste_kernel(
    const float4* __restrict__ in4,
    const float*  __restrict__ patch,
    float4*       __restrict__ out4)
{
    __shared__ int4   sb[NBOX];
    __shared__ float2 sf[NBOX];

    int b = blockIdx.x >> 8;               // 256 blocks per image
    if (threadIdx.x < NBOX) {
        sb[threadIdx.x] = g_box[b * NBOX + threadIdx.x];
        sf[threadIdx.x] = g_scl[b * NBOX + threadIdx.x];
    }
    __syncthreads();

    int gid = blockIdx.x * 256 + threadIdx.x;   // quad id
    int rem = gid & 65535;                      // quad within image (H*W/4 = 65536)
    int y   = rem >> 7;                         // 128 quads per row
    int x0  = (rem & 127) << 2;

    // Which box (if any) covers each of the 4 pixels: highest n wins.
    int cover[4] = {-1, -1, -1, -1};
    #pragma unroll
    for (int n = NBOX - 1; n >= 0; --n) {
        int4 bx = sb[n];
        if ((unsigned)(y - bx.x) < (unsigned)bx.z) {
            #pragma unroll
            for (int k = 0; k < 4; ++k)
                if (cover[k] < 0 && (unsigned)(x0 + k - bx.y) < (unsigned)bx.w)
                    cover[k] = n;
        }
    }

    float v[12];
    int mn = min(min(cover[0], cover[1]), min(cover[2], cover[3]));
    size_t base = (size_t)gid * 3u;

    if (mn < 0) {  // at least one uncovered pixel -> need the input image
        float4 a = in4[base + 0];
        float4 c = in4[base + 1];
        float4 d = in4[base + 2];
        v[0] = a.x; v[1]  = a.y; v[2]  = a.z; v[3]  = a.w;
        v[4] = c.x; v[5]  = c.y; v[6]  = c.z; v[7]  = c.w;
        v[8] = d.x; v[9]  = d.y; v[10] = d.z; v[11] = d.w;
    }

    #pragma unroll
    for (int k = 0; k < 4; ++k) {
        int n = cover[k];
        if (n >= 0) {
            int4   bx = sb[n];
            float2 f  = sf[n];
            // sy = clip((dy+0.5)*(P/hf) - 0.5, 0, P-1) -- match reference rounding
            float sy = __fsub_rn(__fmul_rn(__fadd_rn((float)(y - bx.x), 0.5f), f.x), 0.5f);
            sy = fminf(fmaxf(sy, 0.0f), (float)(PSZ - 1));
            int   yl = (int)sy;                       // floor (sy >= 0)
            float wy = __fsub_rn(sy, (float)yl);
            int   yh = min(yl + 1, PSZ - 1);

            float sx = __fsub_rn(__fmul_rn(__fadd_rn((float)(x0 + k - bx.y), 0.5f), f.y), 0.5f);
            sx = fminf(fmaxf(sx, 0.0f), (float)(PSZ - 1));
            int   xl = (int)sx;
            float wx = __fsub_rn(sx, (float)xl);
            int   xh = min(xl + 1, PSZ - 1);

            const float* pl = patch + yl * (PSZ * 3);
            const float* ph = patch + yh * (PSZ * 3);
            float omy = 1.0f - wy;
            float omx = 1.0f - wx;
            #pragma unroll
            for (int c = 0; c < 3; ++c) {
                // separable: y-interp rows, then x-interp (reference order)
                float r0 = pl[xl * 3 + c] * omy + ph[xl * 3 + c] * wy;
                float r1 = pl[xh * 3 + c] * omy + ph[xh * 3 + c] * wy;
                v[k * 3 + c] = r0 * omx + r1 * wx;
            }
        }
    }

    out4[base + 0] = make_float4(v[0], v[1], v[2],  v[3]);
    out4[base + 1] = make_float4(v[4], v[5], v[6],  v[7]);
    out4[base + 2] = make_float4(v[8], v[9], v[10], v[11]);
}

// ---------------------------------------------------------------------------
extern "C" void kernel_launch(void* const* d_in, const int* in_sizes, int n_in,
                              void* d_out, int out_size) {
    const float* images = (const float*)d_in[0];
    const float* boxes  = (n_in > 1) ? (const float*)d_in[1] : nullptr;
    const float* patch  = (n_in > 2) ? (const float*)d_in[2] : nullptr;
    // Robustly identify inputs by element count.
    for (int i = 0; i < n_in; ++i) {
        if (in_sizes[i] == BATCH * NBOX * 4)           boxes  = (const float*)d_in[i];
        else if (in_sizes[i] == PSZ * PSZ * 3)         patch  = (const float*)d_in[i];
        else if (in_sizes[i] == BATCH * IMH * IMW * 3) images = (const float*)d_in[i];
    }

    prep_kernel<<<1, BATCH * NBOX>>>(boxes);
    paste_kernel<<<BATCH * 256, 256>>>((const float4*)images, patch, (float4*)d_out);
}

// round 7
// speedup vs baseline: 1.1040x; 1.1040x over previous
#include <cuda_runtime.h>

#define BATCH 32
#define IMH   512
#define IMW   512
#define NBOX  6
#define PSZ   512

// Per-box precomputed data: int4 = (y0, x0, h, w) [h=0 when invalid],
// float2 = (512/hf, 512/wf)
__device__ int4   g_box[BATCH * NBOX];
__device__ float2 g_scl[BATCH * NBOX];
// Patch repacked RGB -> RGBA so each texel is a single 16B-aligned LDG.128.
__device__ float4 g_patch4[PSZ * PSZ];

// ---------------------------------------------------------------------------
// Prep: replicate _patch_boxes + int casts bit-exactly (no FMA contraction).
// boxes layout: [B, N, 4] = (ymin, xmin, ymax, xmax)
// ---------------------------------------------------------------------------
__global__ void prep_kernel(const float* __restrict__ boxes) {
    int i = blockIdx.x * blockDim.x + threadIdx.x;
    if (i >= BATCH * NBOX) return;
    float ymin = boxes[i * 4 + 0];
    float xmin = boxes[i * 4 + 1];
    float ymax = boxes[i * 4 + 2];
    float xmax = boxes[i * 4 + 3];

    float h  = __fsub_rn(ymax, ymin);
    float w  = __fsub_rn(xmax, xmin);
    float pw = __fmul_rn(h, 0.5f);        // SCALE = 0.5
    float ph = pw;                         // ASPECT = 1.0 (exact)
    float oy = __fadd_rn(ymin, __fmul_rn(h, 0.5f));
    float ox = __fadd_rn(xmin, __fmul_rn(w, 0.5f));
    float yp = fmaxf(__fsub_rn(oy, __fmul_rn(ph, 0.5f)), 0.0f);
    float xp = fmaxf(__fsub_rn(ox, __fmul_rn(pw, 0.5f)), 0.0f);
    if (__fadd_rn(yp, ph) > (float)IMH) yp = __fsub_rn((float)IMH, ph);
    if (__fadd_rn(xp, pw) > (float)IMW) xp = __fsub_rn((float)IMW, pw);
    bool valid = (ph > 60.0f);             // MIN_PH

    int y0 = (int)yp;                      // astype(int32) = truncation (nonneg)
    int x0 = (int)xp;
    int hi = (int)ph;
    int wi = (int)pw;

    int4 bx;
    bx.x = y0; bx.y = x0;
    bx.z = valid ? hi : 0;                 // h=0 kills the inside test
    bx.w = wi;
    g_box[i] = bx;

    float2 f;
    f.x = __fdiv_rn((float)PSZ, (float)max(hi, 1));
    f.y = __fdiv_rn((float)PSZ, (float)max(wi, 1));
    g_scl[i] = f;
}

// ---------------------------------------------------------------------------
// Repack patch [512,512,3] f32 -> [512,512] float4 (alpha unused).
// One thread per texel; reads are contiguous across the warp, write is
// perfectly coalesced 16B stores.
// ---------------------------------------------------------------------------
__global__ __launch_bounds__(256) void repack_kernel(const float* __restrict__ patch) {
    int i = blockIdx.x * 256 + threadIdx.x;   // texel id, 0..262143
    const float* s = patch + (size_t)i * 3u;
    g_patch4[i] = make_float4(s[0], s[1], s[2], 0.0f);
}

// ---------------------------------------------------------------------------
// Main paste kernel: 1 thread = 4 consecutive pixels (3 x float4 in/out).
// 256 blocks per image -> single batch index per block.
// Gather path: 4 x LDG.128 per covered pixel (one 32B sector each).
// ---------------------------------------------------------------------------
__global__ __launch_bounds__(256) void paste_kernel(
    const float4* __restrict__ in4,
    float4*       __restrict__ out4)
{
    __shared__ int4   sb[NBOX];
    __shared__ float2 sf[NBOX];

    int b = blockIdx.x >> 8;               // 256 blocks per image
    if (threadIdx.x < NBOX) {
        sb[threadIdx.x] = g_box[b * NBOX + threadIdx.x];
        sf[threadIdx.x] = g_scl[b * NBOX + threadIdx.x];
    }
    __syncthreads();

    int gid = blockIdx.x * 256 + threadIdx.x;   // quad id
    int rem = gid & 65535;                      // quad within image (H*W/4 = 65536)
    int y   = rem >> 7;                         // 128 quads per row
    int x0  = (rem & 127) << 2;

    // Which box (if any) covers each of the 4 pixels: highest n wins.
    int cover[4] = {-1, -1, -1, -1};
    #pragma unroll
    for (int n = NBOX - 1; n >= 0; --n) {
        int4 bx = sb[n];
        if ((unsigned)(y - bx.x) < (unsigned)bx.z) {
            #pragma unroll
            for (int k = 0; k < 4; ++k)
                if (cover[k] < 0 && (unsigned)(x0 + k - bx.y) < (unsigned)bx.w)
                    cover[k] = n;
        }
    }

    float v[12];
    int mn = min(min(cover[0], cover[1]), min(cover[2], cover[3]));
    size_t base = (size_t)gid * 3u;

    if (mn < 0) {  // at least one uncovered pixel -> need the input image
        float4 a = in4[base + 0];
        float4 c = in4[base + 1];
        float4 d = in4[base + 2];
        v[0] = a.x; v[1]  = a.y; v[2]  = a.z; v[3]  = a.w;
        v[4] = c.x; v[5]  = c.y; v[6]  = c.z; v[7]  = c.w;
        v[8] = d.x; v[9]  = d.y; v[10] = d.z; v[11] = d.w;
    }

    #pragma unroll
    for (int k = 0; k < 4; ++k) {
        int n = cover[k];
        if (n >= 0) {
            int4   bx = sb[n];
            float2 f  = sf[n];
            // sy = clip((dy+0.5)*(P/hf) - 0.5, 0, P-1) -- match reference rounding
            float sy = __fsub_rn(__fmul_rn(__fadd_rn((float)(y - bx.x), 0.5f), f.x), 0.5f);
            sy = fminf(fmaxf(sy, 0.0f), (float)(PSZ - 1));
            int   yl = (int)sy;                       // floor (sy >= 0)
            float wy = __fsub_rn(sy, (float)yl);
            int   yh = min(yl + 1, PSZ - 1);

            float sx = __fsub_rn(__fmul_rn(__fadd_rn((float)(x0 + k - bx.y), 0.5f), f.y), 0.5f);
            sx = fminf(fmaxf(sx, 0.0f), (float)(PSZ - 1));
            int   xl = (int)sx;
            float wx = __fsub_rn(sx, (float)xl);
            int   xh = min(xl + 1, PSZ - 1);

            const float4* pl = g_patch4 + yl * PSZ;
            const float4* ph = g_patch4 + yh * PSZ;
            float4 t00 = pl[xl];
            float4 t01 = pl[xh];
            float4 t10 = ph[xl];
            float4 t11 = ph[xh];

            float omy = 1.0f - wy;
            float omx = 1.0f - wx;
            // separable: y-interp rows first, then x-interp (reference order):
            //   r0 = t00*omy + t10*wy ; r1 = t01*omy + t11*wy ; v = r0*omx + r1*wx
            float r0x = t00.x * omy + t10.x * wy;
            float r0y = t00.y * omy + t10.y * wy;
            float r0z = t00.z * omy + t10.z * wy;
            float r1x = t01.x * omy + t11.x * wy;
            float r1y = t01.y * omy + t11.y * wy;
            float r1z = t01.z * omy + t11.z * wy;
            v[k * 3 + 0] = r0x * omx + r1x * wx;
            v[k * 3 + 1] = r0y * omx + r1y * wx;
            v[k * 3 + 2] = r0z * omx + r1z * wx;
        }
    }

    out4[base + 0] = make_float4(v[0], v[1], v[2],  v[3]);
    out4[base + 1] = make_float4(v[4], v[5], v[6],  v[7]);
    out4[base + 2] = make_float4(v[8], v[9], v[10], v[11]);
}

// ---------------------------------------------------------------------------
extern "C" void kernel_launch(void* const* d_in, const int* in_sizes, int n_in,
                              void* d_out, int out_size) {
    const float* images = (const float*)d_in[0];
    const float* boxes  = (n_in > 1) ? (const float*)d_in[1] : nullptr;
    const float* patch  = (n_in > 2) ? (const float*)d_in[2] : nullptr;
    // Robustly identify inputs by element count.
    for (int i = 0; i < n_in; ++i) {
        if (in_sizes[i] == BATCH * NBOX * 4)           boxes  = (const float*)d_in[i];
        else if (in_sizes[i] == PSZ * PSZ * 3)         patch  = (const float*)d_in[i];
        else if (in_sizes[i] == BATCH * IMH * IMW * 3) images = (const float*)d_in[i];
    }

    prep_kernel<<<1, BATCH * NBOX>>>(boxes);
    repack_kernel<<<(PSZ * PSZ) / 256, 256>>>(patch);
    paste_kernel<<<BATCH * 256, 256>>>((const float4*)images, (float4*)d_out);
}

// round 12
// speedup vs baseline: 1.2374x; 1.1209x over previous
#include <cuda_runtime.h>
#include <cuda_fp16.h>

#define BATCH 32
#define IMH   512
#define IMW   512
#define NBOX  6
#define PSZ   512

// Patch repacked as adjacent-texel pairs in fp16:
// entry (y,x) = { h(r[x]), h(g[x]), h(b[x]), h(r[x2]), h(g[x2]), h(b[x2]), 0, 0 }
// with x2 = min(x+1, 511).  One 16B entry = both x-taps of the bilinear filter,
// so each covered pixel needs exactly 2 LDG.128 (rows yl and yh).
__device__ uint4 g_pair[PSZ * PSZ];

static __device__ __forceinline__ unsigned int h2_bits(half2 h) {
    return *(unsigned int*)&h;
}

// ---------------------------------------------------------------------------
// Repack kernel: [512,512,3] f32 -> pair-packed fp16 entries.
// ---------------------------------------------------------------------------
__global__ __launch_bounds__(256) void repack_kernel(const float* __restrict__ patch) {
    int i = blockIdx.x * 256 + threadIdx.x;   // entry id 0..262143
    int x  = i & (PSZ - 1);
    int x2 = min(x + 1, PSZ - 1);
    const float* s0 = patch + (size_t)i * 3u;
    const float* s1 = patch + ((size_t)(i - x) + x2) * 3u;

    half2 p0 = __floats2half2_rn(s0[0], s0[1]);
    half2 p1 = __floats2half2_rn(s0[2], s1[0]);
    half2 p2 = __floats2half2_rn(s1[1], s1[2]);

    uint4 e;
    e.x = h2_bits(p0);
    e.y = h2_bits(p1);
    e.z = h2_bits(p2);
    e.w = 0u;
    g_pair[i] = e;
}

// ---------------------------------------------------------------------------
// Main paste kernel: 1 thread = 4 consecutive pixels (3 x float4 in/out).
// 256 blocks per image -> single batch index per block.
// Box prep (bit-exact _patch_boxes + int casts, no FMA contraction) is fused:
// threads 0..5 of every block compute their image's 6 box records.
// ---------------------------------------------------------------------------
__global__ __launch_bounds__(256) void paste_kernel(
    const float4* __restrict__ in4,
    const float*  __restrict__ boxes,
    float4*       __restrict__ out4)
{
    __shared__ int4   sb[NBOX];   // (y0, x0, h, w)  h=0 when invalid
    __shared__ float2 sf[NBOX];   // (512/hf, 512/wf)

    int b = blockIdx.x >> 8;      // 256 blocks per image
    if (threadIdx.x < NBOX) {
        int i = b * NBOX + threadIdx.x;
        float ymin = boxes[i * 4 + 0];
        float xmin = boxes[i * 4 + 1];
        float ymax = boxes[i * 4 + 2];
        float xmax = boxes[i * 4 + 3];

        float h  = __fsub_rn(ymax, ymin);
        float w  = __fsub_rn(xmax, xmin);
        float pw = __fmul_rn(h, 0.5f);        // SCALE = 0.5
        float ph = pw;                         // ASPECT = 1.0 (exact)
        float oy = __fadd_rn(ymin, __fmul_rn(h, 0.5f));
        float ox = __fadd_rn(xmin, __fmul_rn(w, 0.5f));
        float yp = fmaxf(__fsub_rn(oy, __fmul_rn(ph, 0.5f)), 0.0f);
        float xp = fmaxf(__fsub_rn(ox, __fmul_rn(pw, 0.5f)), 0.0f);
        if (__fadd_rn(yp, ph) > (float)IMH) yp = __fsub_rn((float)IMH, ph);
        if (__fadd_rn(xp, pw) > (float)IMW) xp = __fsub_rn((float)IMW, pw);
        bool valid = (ph > 60.0f);             // MIN_PH

        int y0  = (int)yp;                     // astype(int32) = truncation
        int x0i = (int)xp;
        int hi  = (int)ph;
        int wi  = (int)pw;

        int4 bx;
        bx.x = y0; bx.y = x0i;
        bx.z = valid ? hi : 0;
        bx.w = wi;
        sb[threadIdx.x] = bx;

        float2 f;
        f.x = __fdiv_rn((float)PSZ, (float)max(hi, 1));
        f.y = __fdiv_rn((float)PSZ, (float)max(wi, 1));
        sf[threadIdx.x] = f;
    }
    __syncthreads();

    int gid = blockIdx.x * 256 + threadIdx.x;   // quad id
    int rem = gid & 65535;                      // quad within image
    int y   = rem >> 7;                         // 128 quads per row
    int x0  = (rem & 127) << 2;

    // Which box (if any) covers each of the 4 pixels: highest n wins.
    int cover[4] = {-1, -1, -1, -1};
    #pragma unroll
    for (int n = NBOX - 1; n >= 0; --n) {
        int4 bx = sb[n];
        if ((unsigned)(y - bx.x) < (unsigned)bx.z) {
            #pragma unroll
            for (int k = 0; k < 4; ++k)
                if (cover[k] < 0 && (unsigned)(x0 + k - bx.y) < (unsigned)bx.w)
                    cover[k] = n;
        }
    }

    float v[12];
    int mn = min(min(cover[0], cover[1]), min(cover[2], cover[3]));
    size_t base = (size_t)gid * 3u;

    if (mn < 0) {  // at least one uncovered pixel -> need the input image
        float4 a = in4[base + 0];
        float4 c = in4[base + 1];
        float4 d = in4[base + 2];
        v[0] = a.x; v[1]  = a.y; v[2]  = a.z; v[3]  = a.w;
        v[4] = c.x; v[5]  = c.y; v[6]  = c.z; v[7]  = c.w;
        v[8] = d.x; v[9]  = d.y; v[10] = d.z; v[11] = d.w;
    }

    #pragma unroll
    for (int k = 0; k < 4; ++k) {
        int n = cover[k];
        if (n >= 0) {
            int4   bx = sb[n];
            float2 f  = sf[n];
            // sy = clip((dy+0.5)*(P/hf) - 0.5, 0, P-1) -- reference rounding
            float sy = __fsub_rn(__fmul_rn(__fadd_rn((float)(y - bx.x), 0.5f), f.x), 0.5f);
            sy = fminf(fmaxf(sy, 0.0f), (float)(PSZ - 1));
            int   yl = (int)sy;
            float wy = __fsub_rn(sy, (float)yl);
            int   yh = min(yl + 1, PSZ - 1);

            float sx = __fsub_rn(__fmul_rn(__fadd_rn((float)(x0 + k - bx.y), 0.5f), f.y), 0.5f);
            sx = fminf(fmaxf(sx, 0.0f), (float)(PSZ - 1));
            int   xl = (int)sx;
            float wx = __fsub_rn(sx, (float)xl);
            // xh = xl+1 clamp is baked into the pair packing.

            // 2 gathers per pixel: rows yl and yh, each entry holds (xl, xh).
            uint4 eL = g_pair[yl * PSZ + xl];
            uint4 eH = g_pair[yh * PSZ + xl];

            float2 l0 = __half22float2(*(half2*)&eL.x);  // r0,g0
            float2 l1 = __half22float2(*(half2*)&eL.y);  // b0,r1
            float2 l2 = __half22float2(*(half2*)&eL.z);  // g1,b1
            float2 h0 = __half22float2(*(half2*)&eH.x);
            float2 h1 = __half22float2(*(half2*)&eH.y);
            float2 h2 = __half22float2(*(half2*)&eH.z);

            float omy = 1.0f - wy;
            float omx = 1.0f - wx;
            // y-interp rows first, then x-interp (reference order)
            float r0x = l0.x * omy + h0.x * wy;   // texel xl, ch r
            float r0y = l0.y * omy + h0.y * wy;   // xl, g
            float r0z = l1.x * omy + h1.x * wy;   // xl, b
            float r1x = l1.y * omy + h1.y * wy;   // xh, r
            float r1y = l2.x * omy + h2.x * wy;   // xh, g
            float r1z = l2.y * omy + h2.y * wy;   // xh, b
            v[k * 3 + 0] = r0x * omx + r1x * wx;
            v[k * 3 + 1] = r0y * omx + r1y * wx;
            v[k * 3 + 2] = r0z * omx + r1z * wx;
        }
    }

    out4[base + 0] = make_float4(v[0], v[1], v[2],  v[3]);
    out4[base + 1] = make_float4(v[4], v[5], v[6],  v[7]);
    out4[base + 2] = make_float4(v[8], v[9], v[10], v[11]);
}

// ---------------------------------------------------------------------------
extern "C" void kernel_launch(void* const* d_in, const int* in_sizes, int n_in,
                              void* d_out, int out_size) {
    const float* images = (const float*)d_in[0];
    const float* boxes  = (n_in > 1) ? (const float*)d_in[1] : nullptr;
    const float* patch  = (n_in > 2) ? (const float*)d_in[2] : nullptr;
    // Robustly identify inputs by element count.
    for (int i = 0; i < n_in; ++i) {
        if (in_sizes[i] == BATCH * NBOX * 4)           boxes  = (const float*)d_in[i];
        else if (in_sizes[i] == PSZ * PSZ * 3)         patch  = (const float*)d_in[i];
        else if (in_sizes[i] == BATCH * IMH * IMW * 3) images = (const float*)d_in[i];
    }

    repack_kernel<<<(PSZ * PSZ) / 256, 256>>>(patch);
    paste_kernel<<<BATCH * 256, 256>>>((const float4*)images, boxes, (float4*)d_out);
}

// round 17
// speedup vs baseline: 1.2869x; 1.0400x over previous
#include <cuda_runtime.h>
#include <cuda_fp16.h>

#define BATCH 32
#define IMH   512
#define IMW   512
#define NBOX  6
#define PSZ   512

// Patch repacked as adjacent-texel pairs in fp16:
// entry (y,x) = { h(r[x]), h(g[x]), h(b[x]), h(r[x2]), h(g[x2]), h(b[x2]), 0, 0 }
// with x2 = min(x+1, 511).  One 16B entry = both x-taps of the bilinear filter,
// so each covered pixel needs exactly 2 LDG.128 (rows yl and yh).
__device__ uint4 g_pair[PSZ * PSZ];

static __device__ __forceinline__ unsigned int h2_bits(half2 h) {
    return *(unsigned int*)&h;
}

// ---------------------------------------------------------------------------
// Repack kernel: [512,512,3] f32 -> pair-packed fp16 entries.
// ---------------------------------------------------------------------------
__global__ __launch_bounds__(256) void repack_kernel(const float* __restrict__ patch) {
    int i = blockIdx.x * 256 + threadIdx.x;   // entry id 0..262143
    int x  = i & (PSZ - 1);
    int x2 = min(x + 1, PSZ - 1);
    const float* s0 = patch + (size_t)i * 3u;
    const float* s1 = patch + ((size_t)(i - x) + x2) * 3u;

    half2 p0 = __floats2half2_rn(s0[0], s0[1]);
    half2 p1 = __floats2half2_rn(s0[2], s1[0]);
    half2 p2 = __floats2half2_rn(s1[1], s1[2]);

    uint4 e;
    e.x = h2_bits(p0);
    e.y = h2_bits(p1);
    e.z = h2_bits(p2);
    e.w = 0u;
    g_pair[i] = e;
}

// ---------------------------------------------------------------------------
// Main paste kernel: 1 thread = 4 consecutive pixels (3 x float4 in/out).
// 256 blocks per image -> single batch index per block.
// Box prep (bit-exact _patch_boxes + int casts, no FMA contraction) is fused:
// threads 0..5 of every block compute their image's 6 box records.
// Gather path is branchless: uncovered pixels sample a clamped dummy box
// (warp-uniform L1-hit broadcasts) so all loads in a 2-pixel batch issue
// back-to-back (MLP 4) with no BSSY/BSYNC fences.
// ---------------------------------------------------------------------------
__global__ __launch_bounds__(256) void paste_kernel(
    const float4* __restrict__ in4,
    const float*  __restrict__ boxes,
    float4*       __restrict__ out4)
{
    __shared__ int4   sb[NBOX];   // (y0, x0, h, w)  h=0 when invalid
    __shared__ float2 sf[NBOX];   // (512/hf, 512/wf)

    int b = blockIdx.x >> 8;      // 256 blocks per image
    if (threadIdx.x < NBOX) {
        int i = b * NBOX + threadIdx.x;
        float ymin = boxes[i * 4 + 0];
        float xmin = boxes[i * 4 + 1];
        float ymax = boxes[i * 4 + 2];
        float xmax = boxes[i * 4 + 3];

        float h  = __fsub_rn(ymax, ymin);
        float w  = __fsub_rn(xmax, xmin);
        float pw = __fmul_rn(h, 0.5f);        // SCALE = 0.5
        float ph = pw;                         // ASPECT = 1.0 (exact)
        float oy = __fadd_rn(ymin, __fmul_rn(h, 0.5f));
        float ox = __fadd_rn(xmin, __fmul_rn(w, 0.5f));
        float yp = fmaxf(__fsub_rn(oy, __fmul_rn(ph, 0.5f)), 0.0f);
        float xp = fmaxf(__fsub_rn(ox, __fmul_rn(pw, 0.5f)), 0.0f);
        if (__fadd_rn(yp, ph) > (float)IMH) yp = __fsub_rn((float)IMH, ph);
        if (__fadd_rn(xp, pw) > (float)IMW) xp = __fsub_rn((float)IMW, pw);
        bool valid = (ph > 60.0f);             // MIN_PH

        int y0  = (int)yp;                     // astype(int32) = truncation
        int x0i = (int)xp;
        int hi  = (int)ph;
        int wi  = (int)pw;

        int4 bx;
        bx.x = y0; bx.y = x0i;
        bx.z = valid ? hi : 0;
        bx.w = wi;
        sb[threadIdx.x] = bx;

        float2 f;
        f.x = __fdiv_rn((float)PSZ, (float)max(hi, 1));
        f.y = __fdiv_rn((float)PSZ, (float)max(wi, 1));
        sf[threadIdx.x] = f;
    }
    __syncthreads();

    int gid = blockIdx.x * 256 + threadIdx.x;   // quad id
    int rem = gid & 65535;                      // quad within image
    int y   = rem >> 7;                         // 128 quads per row
    int x0  = (rem & 127) << 2;

    // Which box (if any) covers each of the 4 pixels: highest n wins.
    int cover[4] = {-1, -1, -1, -1};
    #pragma unroll
    for (int n = NBOX - 1; n >= 0; --n) {
        int4 bx = sb[n];
        if ((unsigned)(y - bx.x) < (unsigned)bx.z) {
            #pragma unroll
            for (int k = 0; k < 4; ++k)
                if (cover[k] < 0 && (unsigned)(x0 + k - bx.y) < (unsigned)bx.w)
                    cover[k] = n;
        }
    }

    float v[12];
    int mn = min(min(cover[0], cover[1]), min(cover[2], cover[3]));
    size_t base = (size_t)gid * 3u;

    if (mn < 0) {  // at least one uncovered pixel -> need the input image
        float4 a = __ldcs(&in4[base + 0]);     // stream-once: evict-first
        float4 c = __ldcs(&in4[base + 1]);
        float4 d = __ldcs(&in4[base + 2]);
        v[0] = a.x; v[1]  = a.y; v[2]  = a.z; v[3]  = a.w;
        v[4] = c.x; v[5]  = c.y; v[6]  = c.z; v[7]  = c.w;
        v[8] = d.x; v[9]  = d.y; v[10] = d.z; v[11] = d.w;
    }

    // Branchless gather in two 2-pixel batches: issue 4 LDG.128 together,
    // then interpolate + select.
    #pragma unroll
    for (int p = 0; p < 2; ++p) {
        uint4 eL[2], eH[2];
        float wyv[2], wxv[2];

        #pragma unroll
        for (int j = 0; j < 2; ++j) {
            int k = p * 2 + j;
            int n = max(cover[k], 0);          // dummy box 0 when uncovered
            int4   bx = sb[n];
            float2 f  = sf[n];
            // sy = clip((dy+0.5)*(P/hf) - 0.5, 0, P-1) -- reference rounding
            float sy = __fsub_rn(__fmul_rn(__fadd_rn((float)(y - bx.x), 0.5f), f.x), 0.5f);
            sy = fminf(fmaxf(sy, 0.0f), (float)(PSZ - 1));
            int   yl = (int)sy;
            wyv[j]   = __fsub_rn(sy, (float)yl);
            int   yh = min(yl + 1, PSZ - 1);

            float sx = __fsub_rn(__fmul_rn(__fadd_rn((float)(x0 + k - bx.y), 0.5f), f.y), 0.5f);
            sx = fminf(fmaxf(sx, 0.0f), (float)(PSZ - 1));
            int   xl = (int)sx;
            wxv[j]   = __fsub_rn(sx, (float)xl);
            // xh = xl+1 clamp is baked into the pair packing.

            eL[j] = g_pair[yl * PSZ + xl];
            eH[j] = g_pair[yh * PSZ + xl];
        }

        #pragma unroll
        for (int j = 0; j < 2; ++j) {
            int k = p * 2 + j;
            float2 l0 = __half22float2(*(half2*)&eL[j].x);  // r0,g0
            float2 l1 = __half22float2(*(half2*)&eL[j].y);  // b0,r1
            float2 l2 = __half22float2(*(half2*)&eL[j].z);  // g1,b1
            float2 h0 = __half22float2(*(half2*)&eH[j].x);
            float2 h1 = __half22float2(*(half2*)&eH[j].y);
            float2 h2 = __half22float2(*(half2*)&eH[j].z);

            float wy = wyv[j], wx = wxv[j];
            float omy = 1.0f - wy;
            float omx = 1.0f - wx;
            // y-interp rows first, then x-interp (reference order)
            float r0x = l0.x * omy + h0.x * wy;   // texel xl, ch r
            float r0y = l0.y * omy + h0.y * wy;   // xl, g
            float r0z = l1.x * omy + h1.x * wy;   // xl, b
            float r1x = l1.y * omy + h1.y * wy;   // xh, r
            float r1y = l2.x * omy + h2.x * wy;   // xh, g
            float r1z = l2.y * omy + h2.y * wy;   // xh, b

            bool cov = (cover[k] >= 0);
            v[k * 3 + 0] = cov ? (r0x * omx + r1x * wx) : v[k * 3 + 0];
            v[k * 3 + 1] = cov ? (r0y * omx + r1y * wx) : v[k * 3 + 1];
            v[k * 3 + 2] = cov ? (r0z * omx + r1z * wx) : v[k * 3 + 2];
        }
    }

    __stcs(&out4[base + 0], make_float4(v[0], v[1], v[2],  v[3]));
    __stcs(&out4[base + 1], make_float4(v[4], v[5], v[6],  v[7]));
    __stcs(&out4[base + 2], make_float4(v[8], v[9], v[10], v[11]));
}

// ---------------------------------------------------------------------------
extern "C" void kernel_launch(void* const* d_in, const int* in_sizes, int n_in,
                              void* d_out, int out_size) {
    const float* images = (const float*)d_in[0];
    const float* boxes  = (n_in > 1) ? (const float*)d_in[1] : nullptr;
    const float* patch  = (n_in > 2) ? (const float*)d_in[2] : nullptr;
    // Robustly identify inputs by element count.
    for (int i = 0; i < n_in; ++i) {
        if (in_sizes[i] == BATCH * NBOX * 4)           boxes  = (const float*)d_in[i];
        else if (in_sizes[i] == PSZ * PSZ * 3)         patch  = (const float*)d_in[i];
        else if (in_sizes[i] == BATCH * IMH * IMW * 3) images = (const float*)d_in[i];
    }

    repack_kernel<<<(PSZ * PSZ) / 256, 256>>>(patch);
    paste_kernel<<<BATCH * 256, 256>>>((const float4*)images, boxes, (float4*)d_out);
}